// round 10
// baseline (speedup 1.0000x reference)
#include <cuda_runtime.h>
#include <cuda_bf16.h>
#include <cuda_fp16.h>
#include <cstdint>

// PolyConv: h = sum_k theta[k] * L_sym^k x, L_sym = I - D^{-1/2} A D^{-1/2}
// N=100000 nodes, E=1600000 edges, F=64 features, k=0..4.
// Gather operand is an fp16 mirror of feat*dinv (pre-scaled, PING-PONGED to
// avoid read/write races); accumulation, identity term, and output stay fp32.

#define NN 100000
#define EE 1600000
#define FF 64

// ---- persistent device scratch (allocation-free rule) ----
__device__ int     g_idx64;                 // 1 if edge_index is int64, 0 if int32
__device__ int     g_total;                 // CSR allocation cursor
__device__ int     g_cnt[NN];               // in-degree
__device__ int     g_beg[NN];               // row segment start
__device__ int     g_rank[EE];              // per-edge rank within its dst row
__device__ int     g_csr[EE];               // src indices grouped by dst
__device__ float   g_dinv[NN];              // rsqrt(max(deg,1))
__device__ float   g_feat[2][NN * FF];      // fp32 ping-pong feature buffers
__device__ __half2 g_mir[2][NN * (FF / 2)]; // fp16 mirror ping-pong (gather operand)

__device__ __forceinline__ int load_idx(const void* __restrict__ ei, int i) {
    if (g_idx64) return (int)((const long long*)ei)[i];
    return ((const int*)ei)[i];
}

// ---------------------------------------------------------------------------
// 0) detect index width (int64 values < 2^31 have zero hi-words).
__global__ void k_detect(const int* __restrict__ ei32) {
    if (threadIdx.x == 0) {
        int is64 = 1;
        for (int i = 0; i < 64; i++)
            if (ei32[2 * i + 1] != 0) { is64 = 0; break; }
        g_idx64 = is64;
    }
}

// 1) in-degree histogram over dst; record each edge's rank within its row.
__global__ void k_hist(const void* __restrict__ ei) {
    int base = (blockIdx.x * blockDim.x + threadIdx.x) * 4;
    #pragma unroll
    for (int j = 0; j < 4; j++) {
        int e = base + j;
        if (e < EE) {
            int dst = load_idx(ei, EE + e);
            g_rank[e] = atomicAdd(&g_cnt[dst], 1);
        }
    }
}

// 2) segment allocation with warp-aggregated cursor (1 atomic / 32 rows)
__global__ void k_alloc() {
    int i = blockIdx.x * blockDim.x + threadIdx.x;
    int lane = threadIdx.x & 31;
    int c = (i < NN) ? g_cnt[i] : 0;

    int inc = c;
    #pragma unroll
    for (int off = 1; off < 32; off <<= 1) {
        int t = __shfl_up_sync(0xffffffffu, inc, off);
        if (lane >= off) inc += t;
    }
    int warpTotal = __shfl_sync(0xffffffffu, inc, 31);
    int base = 0;
    if (lane == 31) base = atomicAdd(&g_total, warpTotal);
    base = __shfl_sync(0xffffffffu, base, 31);

    if (i < NN) {
        g_beg[i] = base + inc - c;
        g_dinv[i] = rsqrtf((float)(c < 1 ? 1 : c));
    }
}

// 3) fill CSR without atomics: position = beg[dst] + rank[e]
__global__ void k_fill(const void* __restrict__ ei) {
    int base = (blockIdx.x * blockDim.x + threadIdx.x) * 4;
    #pragma unroll
    for (int j = 0; j < 4; j++) {
        int e = base + j;
        if (e < EE) {
            int src = load_idx(ei, e);
            int dst = load_idx(ei, EE + e);
            g_csr[g_beg[dst] + g_rank[e]] = src;
        }
    }
}

// 4) build initial fp16 mirror: mir0 = fp16(x * dinv).
__global__ void k_prep(const float* __restrict__ x) {
    int i = blockIdx.x * blockDim.x + threadIdx.x;   // [0, NN*32)
    if (i >= NN * 32) return;
    float d = g_dinv[i >> 5];
    float2 v = ((const float2*)x)[i];
    g_mir[0][i] = __floats2half2_rn(v.x * d, v.y * d);
}

// 5) fused SpMV + epilogue. One warp per row; lane owns features {2*lane, 2*lane+1}.
//    agg = sum over row of mir_in[s] (pre-scaled by dinv[s])
//    feat_new = feat - dinv[r] * agg
//    FIRST: out = theta0*feat + theta*feat_new   else: out += theta*feat_new
//    LAST=0: write fp32 fout and next mirror into mir_out (other buffer).
template <int FIRST, int LAST, int MIN>
__global__ void __launch_bounds__(256) k_spmv(const float* __restrict__ fin,
                                              float* __restrict__ fout,
                                              float* __restrict__ out,
                                              float theta0, float theta) {
    int gtid = blockIdx.x * blockDim.x + threadIdx.x;
    int row  = gtid >> 5;
    int lane = gtid & 31;
    if (row >= NN) return;

    const __half2* __restrict__ mir_in = g_mir[MIN];
    __half2* __restrict__ mir_out      = g_mir[1 - MIN];

    int beg = g_beg[row];
    int end = beg + g_cnt[row];

    float accx = 0.f, accy = 0.f;

    int e = beg;
    for (; e + 2 <= end; e += 2) {
        int s0 = g_csr[e];
        int s1 = g_csr[e + 1];
        float2 a = __half22float2(mir_in[s0 * 32 + lane]);
        float2 b = __half22float2(mir_in[s1 * 32 + lane]);
        accx += a.x + b.x;
        accy += a.y + b.y;
    }
    if (e < end) {
        int s0 = g_csr[e];
        float2 a = __half22float2(mir_in[s0 * 32 + lane]);
        accx += a.x;
        accy += a.y;
    }

    float dr = g_dinv[row];
    float2 f = __ldg(&((const float2*)fin)[row * 32 + lane]);
    float nx = f.x - dr * accx;
    float ny = f.y - dr * accy;

    if (!LAST) {
        ((float2*)fout)[row * 32 + lane] = make_float2(nx, ny);
        mir_out[row * 32 + lane] = __floats2half2_rn(nx * dr, ny * dr);
    }

    float2* o = (float2*)out + row * 32 + lane;
    if (FIRST) {
        *o = make_float2(theta0 * f.x + theta * nx,
                         theta0 * f.y + theta * ny);
    } else {
        float2 v = *o;
        *o = make_float2(fmaf(theta, nx, v.x), fmaf(theta, ny, v.y));
    }
}

extern "C" void kernel_launch(void* const* d_in, const int* in_sizes, int n_in,
                              void* d_out, int out_size) {
    const float* x   = (const float*)d_in[0];
    const void*  ei  = d_in[1];
    float*       out = (float*)d_out;

    float* feat0; float* feat1;
    cudaGetSymbolAddress((void**)&feat0, g_feat);
    feat1 = feat0 + (size_t)NN * FF;
    int* cnt_ptr;   cudaGetSymbolAddress((void**)&cnt_ptr, g_cnt);
    int* total_ptr; cudaGetSymbolAddress((void**)&total_ptr, g_total);

    const int TB = 256;
    // CSR build
    k_detect<<<1, 32>>>((const int*)ei);
    cudaMemsetAsync(cnt_ptr, 0, NN * sizeof(int));
    cudaMemsetAsync(total_ptr, 0, sizeof(int));
    k_hist<<<(EE / 4 + TB - 1) / TB, TB>>>(ei);
    k_alloc<<<(NN + TB - 1) / TB, TB>>>();
    k_fill<<<(EE / 4 + TB - 1) / TB, TB>>>(ei);
    k_prep<<<(NN * 32 + TB - 1) / TB, TB>>>(x);

    // 4 fused SpMV iterations (theta = 0.6, -0.4, 0.3, -0.2, 0.1)
    // mirror ping-pong: prep->mir0; it1 reads mir0 writes mir1; it2 reads mir1
    // writes mir0; it3 reads mir0 writes mir1; it4 reads mir1 writes none.
    const long long threads = (long long)NN * 32;
    const int blocks = (int)((threads + TB - 1) / TB);
    k_spmv<1, 0, 0><<<blocks, TB>>>(x,     feat0, out, 0.6f, -0.4f);
    k_spmv<0, 0, 1><<<blocks, TB>>>(feat0, feat1, out, 0.0f,  0.3f);
    k_spmv<0, 0, 0><<<blocks, TB>>>(feat1, feat0, out, 0.0f, -0.2f);
    k_spmv<0, 1, 1><<<blocks, TB>>>(feat0, feat1, out, 0.0f,  0.1f);
}